// round 1
// baseline (speedup 1.0000x reference)
#include <cuda_runtime.h>
#include <cstdint>
#include <math.h>

#define NB   8      // batch
#define NI   8      // input capsules
#define CIN  16     // input capsule dim
#define HH   64
#define WWs  64
#define NO   8      // output capsules
#define DCAP 16     // output capsule dim
#define ODIM 128    // NO*DCAP
#define HWs  4096   // HH*WWs

// ---------------- device scratch (static: no runtime allocation) ----------------
__device__ float g_uhat[(size_t)NI * NB * HH * WWs * ODIM];   // [i][n][h][w][od]  134MB
__device__ float g_b [(size_t)NI * NB * NO * HH * WWs];       // [i][n][o][h][w]   8MB
__device__ float g_r [(size_t)NI * NB * NO * HH * WWs];       // same layout        8MB
__device__ float g_t [(size_t)NI * NB * HH * WWs];            // max over o         1MB
__device__ float g_bm[(size_t)NI * NB * HH * WWs];            // boxmax             1MB
__device__ float g_sc[(size_t)NI * NB * HH * WWs];            // sum_o exp          1MB

// ---------------- f32x2 helpers ----------------
__device__ __forceinline__ unsigned long long pk2(float lo, float hi) {
    unsigned long long r;
    asm("mov.b64 %0, {%1, %2};" : "=l"(r) : "r"(__float_as_uint(lo)), "r"(__float_as_uint(hi)));
    return r;
}
__device__ __forceinline__ void upk2(unsigned long long v, float& lo, float& hi) {
    unsigned int a, b;
    asm("mov.b64 {%0, %1}, %2;" : "=r"(a), "=r"(b) : "l"(v));
    lo = __uint_as_float(a); hi = __uint_as_float(b);
}
__device__ __forceinline__ void fma2(unsigned long long& d, unsigned long long a, unsigned long long b) {
    asm("fma.rn.f32x2 %0, %1, %2, %0;" : "+l"(d) : "l"(a), "l"(b));
}

// =================================================================================
// Conv kernel: per block (i, n, h) computes full row (64 w) x 128 od.
// smem: input patch [16c][5 rows][68 cols], weight tile k-major [25][128] double buf
// thread tile: 8 od (pairs, strided) x 8 w, f32x2 accumulators.
// =================================================================================
__global__ void __launch_bounds__(128) conv_kernel(const float* __restrict__ u,
                                                   const float* __restrict__ Wp) {
    __shared__ float patch[CIN * 5 * 68];      // 21760 B *? -> 5440 floats = 21.76KB
    __shared__ float wt[2][25 * 128];          // 25.6 KB

    const int h = blockIdx.x, n = blockIdx.y, i = blockIdx.z;
    const int t = threadIdx.x;

    // ---- load input patch (rows h-2..h+2, cols -2..65, zero padded) ----
    const float* ub = u + ((size_t)(n * NI + i) * CIN) * HWs;
    for (int idx = t; idx < CIN * 5 * 68; idx += 128) {
        int c  = idx / 340;
        int rr = idx - c * 340;
        int r5 = rr / 68;
        int col = rr - r5 * 68;
        int hh = h + r5 - 2;
        int ww = col - 2;
        float v = 0.f;
        if ((unsigned)hh < HH && (unsigned)ww < WWs) v = ub[c * HWs + hh * WWs + ww];
        patch[idx] = v;
    }

    const float* wb = Wp + (size_t)i * ODIM * CIN * 25;

    auto prefetch = [&](int c, int buf) {
        #pragma unroll
        for (int j = 0; j < 25; j++) {
            int idx = t + j * 128;            // 0..3199
            int od = idx / 25, k = idx - od * 25;
            unsigned int s = (unsigned int)__cvta_generic_to_shared(&wt[buf][k * 128 + od]);
            const float* g = wb + od * 400 + c * 25 + k;
            asm volatile("cp.async.ca.shared.global [%0], [%1], 4;" :: "r"(s), "l"(g));
        }
        asm volatile("cp.async.commit_group;" ::: "memory");
    };
    prefetch(0, 0);

    unsigned long long acc[4][8];
    #pragma unroll
    for (int j = 0; j < 4; j++)
        #pragma unroll
        for (int wl = 0; wl < 8; wl++) acc[j][wl] = 0ull;

    const int g_o = t & 15;      // od pair group: od = 2*g_o + 32*j (+0/1)
    const int g_w = t >> 4;      // w group: w = g_w*8 + wl

    for (int c = 0; c < CIN; c++) {
        if (c + 1 < CIN) {
            prefetch(c + 1, (c + 1) & 1);
            asm volatile("cp.async.wait_group 1;" ::: "memory");
        } else {
            asm volatile("cp.async.wait_group 0;" ::: "memory");
        }
        __syncthreads();

        const float* pr  = patch + c * 340 + g_w * 8;
        const float* wtb = wt[c & 1];
        #pragma unroll
        for (int kh = 0; kh < 5; kh++) {
            unsigned long long xd[12];
            #pragma unroll
            for (int q = 0; q < 12; q++) {
                float x = pr[kh * 68 + q];
                xd[q] = pk2(x, x);
            }
            #pragma unroll
            for (int kw = 0; kw < 5; kw++) {
                const unsigned long long* wr =
                    (const unsigned long long*)(wtb + (kh * 5 + kw) * 128) + g_o;
                unsigned long long wv[4];
                #pragma unroll
                for (int j = 0; j < 4; j++) wv[j] = wr[16 * j];
                #pragma unroll
                for (int wl = 0; wl < 8; wl++)
                    #pragma unroll
                    for (int j = 0; j < 4; j++) fma2(acc[j][wl], wv[j], xd[wl + kw]);
            }
        }
        __syncthreads();
    }

    // ---- store u_hat[i][n][h][w][od] (8B coalesced: lanes g_o consecutive) ----
    float* ob = g_uhat + (((size_t)(i * NB + n) * HH + h) * WWs + g_w * 8) * ODIM + 2 * g_o;
    #pragma unroll
    for (int wl = 0; wl < 8; wl++)
        #pragma unroll
        for (int j = 0; j < 4; j++)
            *((unsigned long long*)(ob + (size_t)wl * ODIM + 32 * j)) = acc[j][wl];
}

// =================================================================================
// PV kernel: fused p = sum_i r*u_hat, squash -> v, agreement -> b update (or output)
// block: 8 pixels x 8 output capsules = 64 threads. u_hat staged once through smem.
// mode 0: analytic r (b=0), write b = agree
// mode 1: read r,       b += agree
// mode 2: read r,       write final output [N,O,D,H,W]
// =================================================================================
#define PVP 8
__global__ void __launch_bounds__(64) pv_kernel(float* __restrict__ out, int mode) {
    __shared__ float uh[NI * PVP * 132];      // pitch 132 floats, 33.8KB
    __shared__ float rs[NI * NO * PVP];       // 2KB

    const int n = blockIdx.z, h = blockIdx.y, w0 = blockIdx.x * PVP;
    const int t = threadIdx.x;

    // ---- stage u_hat: 8i x 8pix x 128od, coalesced float4 ----
    for (int i = 0; i < NI; i++) {
        const float4* src = (const float4*)(g_uhat +
            (((size_t)(i * NB + n) * HH + h) * WWs + w0) * ODIM);
        #pragma unroll
        for (int j = 0; j < 4; j++) {
            int idx = t + j * 64;             // 0..255 float4
            int p = idx >> 5, q = idx & 31;
            *(float4*)&uh[(i * PVP + p) * 132 + q * 4] = src[idx];
        }
    }
    if (mode != 0) {
        int i = t >> 3, o = t & 7;
        const float* rb = g_r + ((size_t)(i * NB + n) * NO + o) * HWs + h * WWs + w0;
        #pragma unroll
        for (int p = 0; p < PVP; p++) rs[(i * NO + o) * PVP + p] = rb[p];
    }
    __syncthreads();

    const int o = t >> 3, p = t & 7;
    const int w = w0 + p;

    float r0 = 0.f;
    if (mode == 0) {
        int ch = min(h + 2, HH - 1) - max(h - 2, 0) + 1;
        int cw = min(w + 2, WWs - 1) - max(w - 2, 0) + 1;
        r0 = 1.f / (8.f * (float)(ch * cw));
    }

    unsigned long long pacc[8];
    #pragma unroll
    for (int d2 = 0; d2 < 8; d2++) pacc[d2] = 0ull;

    #pragma unroll
    for (int i = 0; i < NI; i++) {
        float rv = (mode == 0) ? r0 : rs[(i * NO + o) * PVP + p];
        unsigned long long rd = pk2(rv, rv);
        const unsigned long long* uq =
            (const unsigned long long*)&uh[(i * PVP + p) * 132 + o * 16];
        #pragma unroll
        for (int d2 = 0; d2 < 8; d2++) fma2(pacc[d2], uq[d2], rd);
    }

    float pv[16];
    #pragma unroll
    for (int d2 = 0; d2 < 8; d2++) upk2(pacc[d2], pv[2 * d2], pv[2 * d2 + 1]);

    float ns = 0.f;
    #pragma unroll
    for (int d = 0; d < 16; d++) ns += pv[d] * pv[d];
    float scale = ns / ((1.f + ns) * sqrtf(ns + 1e-9f));
    float v[16];
    #pragma unroll
    for (int d = 0; d < 16; d++) v[d] = pv[d] * scale;

    if (mode < 2) {
        unsigned long long vp[8];
        #pragma unroll
        for (int d2 = 0; d2 < 8; d2++) vp[d2] = pk2(v[2 * d2], v[2 * d2 + 1]);
        #pragma unroll
        for (int i = 0; i < NI; i++) {
            const unsigned long long* uq =
                (const unsigned long long*)&uh[(i * PVP + p) * 132 + o * 16];
            unsigned long long aa = 0ull;
            #pragma unroll
            for (int d2 = 0; d2 < 8; d2++) fma2(aa, uq[d2], vp[d2]);
            float alo, ahi; upk2(aa, alo, ahi);
            float a = alo + ahi;
            size_t bi = ((size_t)(i * NB + n) * NO + o) * HWs + h * WWs + w;
            g_b[bi] = (mode == 0) ? a : g_b[bi] + a;
        }
    } else {
        #pragma unroll
        for (int d = 0; d < 16; d++)
            out[(((size_t)n * NO + o) * DCAP + d) * HWs + h * WWs + w] = v[d];
    }
}

// =================================================================================
// R kernels: b -> r  (softmax over (O, 5x5 window) with windowed max subtraction)
//   rk1: t  = max_o b
//   rk2: bm = 5x5 boxmax(t) (valid taps);  sc = sum_o exp(b - bm)
//   rk3: ss = 5x5 boxsum(sc) (valid taps); r = exp(b - bm) / ss
// =================================================================================
__global__ void rk1_kernel() {
    int idx = blockIdx.x * 256 + threadIdx.x;           // 262144 pixels x (i,n)
    int in = idx >> 12, hw = idx & 4095;
    const float* bb = g_b + (size_t)in * NO * HWs + hw;
    float m = bb[0];
    #pragma unroll
    for (int o = 1; o < NO; o++) m = fmaxf(m, bb[(size_t)o * HWs]);
    g_t[idx] = m;
}

__global__ void rk2_kernel() {
    int idx = blockIdx.x * 256 + threadIdx.x;
    int in = idx >> 12, hw = idx & 4095, h = hw >> 6, w = hw & 63;
    const float* tb = g_t + (size_t)in * HWs;
    float m = -3.4e38f;
    #pragma unroll
    for (int dh = -2; dh <= 2; dh++) {
        int hh = h + dh;
        if ((unsigned)hh < HH) {
            #pragma unroll
            for (int dw = -2; dw <= 2; dw++) {
                int ww = w + dw;
                if ((unsigned)ww < WWs) m = fmaxf(m, tb[hh * WWs + ww]);
            }
        }
    }
    const float* bb = g_b + (size_t)in * NO * HWs + hw;
    float s = 0.f;
    #pragma unroll
    for (int o = 0; o < NO; o++) s += __expf(bb[(size_t)o * HWs] - m);
    g_bm[idx] = m;
    g_sc[idx] = s;
}

__global__ void rk3_kernel() {
    int idx = blockIdx.x * 256 + threadIdx.x;
    int in = idx >> 12, hw = idx & 4095, h = hw >> 6, w = hw & 63;
    const float* scb = g_sc + (size_t)in * HWs;
    float ss = 0.f;
    #pragma unroll
    for (int dh = -2; dh <= 2; dh++) {
        int hh = h + dh;
        if ((unsigned)hh < HH) {
            #pragma unroll
            for (int dw = -2; dw <= 2; dw++) {
                int ww = w + dw;
                if ((unsigned)ww < WWs) ss += scb[hh * WWs + ww];
            }
        }
    }
    float bm  = g_bm[idx];
    float inv = 1.f / ss;
    const float* bb = g_b + (size_t)in * NO * HWs + hw;
    float*       rr = g_r + (size_t)in * NO * HWs + hw;
    #pragma unroll
    for (int o = 0; o < NO; o++)
        rr[(size_t)o * HWs] = __expf(bb[(size_t)o * HWs] - bm) * inv;
}

// =================================================================================
extern "C" void kernel_launch(void* const* d_in, const int* in_sizes, int n_in,
                              void* d_out, int out_size) {
    const float* u  = (const float*)d_in[0];   // [8, 8, 16, 64, 64]
    const float* Wp = (const float*)d_in[1];   // [8, 128, 16, 5, 5]
    float* out = (float*)d_out;                // [8, 8, 16, 64, 64]

    conv_kernel<<<dim3(HH, NB, NI), 128>>>(u, Wp);

    // routing iteration 0 (b = 0 -> analytic r)
    pv_kernel<<<dim3(WWs / PVP, HH, NB), 64>>>(out, 0);

    // routing iterations 1, 2
    for (int it = 1; it <= 2; it++) {
        rk1_kernel<<<1024, 256>>>();
        rk2_kernel<<<1024, 256>>>();
        rk3_kernel<<<1024, 256>>>();
        pv_kernel<<<dim3(WWs / PVP, HH, NB), 64>>>(out, it);
    }
}

// round 4
// speedup vs baseline: 2.0548x; 2.0548x over previous
#include <cuda_runtime.h>
#include <cstdint>
#include <math.h>

#define NB   8      // batch
#define NI   8      // input capsules
#define CIN  16     // input capsule dim
#define HH   64
#define WWs  64
#define NO   8      // output capsules
#define DCAP 16     // output capsule dim
#define ODIM 128    // NO*DCAP
#define HWs  4096   // HH*WWs
#define KDIM 416    // 26 positions * 16 c (25 real + 1 zero pad)

// ---------------- device scratch (static: no runtime allocation) ----------------
__device__ float g_uhat[(size_t)NI * NB * HH * WWs * ODIM];   // [i][n][h][w][od]  134MB
__device__ float g_ut  [(size_t)NB * NI * HWs * CIN];         // [n][i][h][w][c]    33MB
__device__ float g_w2  [(size_t)NI * ODIM * KDIM];            // [i][od][p*16+c]   1.7MB
__device__ float g_b [(size_t)NI * NB * NO * HH * WWs];       // [i][n][o][h][w]    8MB
__device__ float g_r [(size_t)NI * NB * NO * HH * WWs];
__device__ float g_t [(size_t)NI * NB * HH * WWs];
__device__ float g_bm[(size_t)NI * NB * HH * WWs];
__device__ float g_sc[(size_t)NI * NB * HH * WWs];

// ---------------- f32x2 helpers (routing kernels) ----------------
__device__ __forceinline__ unsigned long long pk2(float lo, float hi) {
    unsigned long long r;
    asm("mov.b64 %0, {%1, %2};" : "=l"(r) : "r"(__float_as_uint(lo)), "r"(__float_as_uint(hi)));
    return r;
}
__device__ __forceinline__ void upk2(unsigned long long v, float& lo, float& hi) {
    unsigned int a, b;
    asm("mov.b64 {%0, %1}, %2;" : "=r"(a), "=r"(b) : "l"(v));
    lo = __uint_as_float(a); hi = __uint_as_float(b);
}
__device__ __forceinline__ void fma2(unsigned long long& d, unsigned long long a, unsigned long long b) {
    asm("fma.rn.f32x2 %0, %1, %2, %0;" : "+l"(d) : "l"(a), "l"(b));
}

__device__ __forceinline__ uint32_t to_tf32(float f) {
    uint32_t r;
    asm("cvt.rna.tf32.f32 %0, %1;" : "=r"(r) : "f"(f));
    return r;
}

// =================================================================================
// Prep kernels
// =================================================================================
__global__ void __launch_bounds__(256) trans_kernel(const float* __restrict__ u) {
    __shared__ float s[16 * 65];
    const int t = threadIdx.x;
    const float* src = u + (size_t)blockIdx.x * CIN * HWs;   // blockIdx = n*NI+i
    float* dst = g_ut + (size_t)blockIdx.x * HWs * CIN;
    for (int h = 0; h < HH; h++) {
        #pragma unroll
        for (int j = 0; j < 4; j++) {
            int idx = t + j * 256;
            int c = idx >> 6, w = idx & 63;
            s[c * 65 + w] = src[(size_t)c * HWs + h * WWs + w];
        }
        __syncthreads();
        #pragma unroll
        for (int j = 0; j < 4; j++) {
            int idx = t + j * 256;
            int w = idx >> 4, c = idx & 15;
            dst[((size_t)h * WWs + w) * CIN + c] = s[c * 65 + w];
        }
        __syncthreads();
    }
}

__global__ void __launch_bounds__(416) repack_kernel(const float* __restrict__ Wp) {
    const int t = threadIdx.x;         // 0..415  (= p*16 + c)
    const int p = t >> 4, c = t & 15;
    float v = 0.f;
    if (p < 25) v = Wp[((size_t)blockIdx.x * CIN + c) * 25 + p];   // blockIdx = i*128+od
    g_w2[(size_t)blockIdx.x * KDIM + t] = v;
}

// =================================================================================
// Conv via mma.sync m16n8k8 tf32 (sm_80+ path; legal on compute_100).
// CTA = (hp, n, i): M = 128 (rows h0,h0+1 x 64 w), N = 128 od, K = 416.
// smem holds ONE k-chunk (k32) in FRAGMENT-MAJOR layout:
//   sA[((ks*8+mt)*32+L)*4 + j]  : a0=(g,tig) a1=(g+8,tig) a2=(g,tig+4) a3=(g+8,tig+4)
//   sB[((ks*16+nt)*32+L)*2 + j] : b0=(k=tig,n=g) b1=(k=tig+4,n=g)
// Register prefetch of chunk kt+1 overlaps LDG with mma of chunk kt.
// =================================================================================
#define MMA_TF32(d, a, b) \
    asm volatile("mma.sync.aligned.m16n8k8.row.col.f32.tf32.tf32.f32 " \
        "{%0,%1,%2,%3}, {%4,%5,%6,%7}, {%8,%9}, {%0,%1,%2,%3};" \
        : "+f"((d)[0]), "+f"((d)[1]), "+f"((d)[2]), "+f"((d)[3]) \
        : "r"((a).x), "r"((a).y), "r"((a).z), "r"((a).w), "r"((b).x), "r"((b).y))

__global__ void __launch_bounds__(256) conv_mma_kernel() {
    __shared__ float sA[4096];     // 16KB: one chunk A fragments
    __shared__ float sB[4096];     // 16KB: one chunk B fragments

    const int hp = blockIdx.x, nb = blockIdx.y, ic = blockIdx.z;
    const int h0 = hp * 2;
    const int t = threadIdx.x;
    const int lane = t & 31, wid = t >> 5;
    const int g = lane >> 2, tig = lane & 3;
    const int wm = wid & 3;        // 0..3 : m quarter (32 rows)
    const int wnn = wid >> 2;      // 0..1 : n half (64 cols)

    const float* ut = g_ut + (size_t)(nb * NI + ic) * HWs * CIN;
    const float* wb = g_w2 + (size_t)ic * ODIM * KDIM;

    float acc[2][8][4];
    #pragma unroll
    for (int a = 0; a < 2; a++)
        #pragma unroll
        for (int b = 0; b < 8; b++)
            #pragma unroll
            for (int c = 0; c < 4; c++) acc[a][b][c] = 0.f;

    float ra[4][4];   // prefetched A values (4 quads)
    float rb[8][2];   // prefetched B values (8 pairs)

    auto loadA = [&](int kt) {
        #pragma unroll
        for (int qi = 0; qi < 4; qi++) {
            int q  = qi * 256 + t;            // 0..1023
            int L  = q & 31;
            int mt = (q >> 5) & 7;
            int ks = q >> 8;
            int gg = L >> 2, tg = L & 3;
            int pos = kt * 2 + (ks >> 1);
            int cc  = ((ks & 1) << 3) + tg;
            int m0  = mt * 16 + gg;
            float v0 = 0.f, v1 = 0.f, v2 = 0.f, v3 = 0.f;
            if (pos < 25) {
                int p5 = pos / 5;
                int dh = p5 - 2, dw = pos - p5 * 5 - 2;
                {
                    int hg = h0 + (m0 >> 6) + dh, wg = (m0 & 63) + dw;
                    if ((unsigned)hg < 64u && (unsigned)wg < 64u) {
                        const float* p = ut + ((size_t)hg * WWs + wg) * CIN;
                        v0 = p[cc]; v2 = p[cc + 4];
                    }
                }
                {
                    int m1 = m0 + 8;
                    int hg = h0 + (m1 >> 6) + dh, wg = (m1 & 63) + dw;
                    if ((unsigned)hg < 64u && (unsigned)wg < 64u) {
                        const float* p = ut + ((size_t)hg * WWs + wg) * CIN;
                        v1 = p[cc]; v3 = p[cc + 4];
                    }
                }
            }
            ra[qi][0] = v0; ra[qi][1] = v1; ra[qi][2] = v2; ra[qi][3] = v3;
        }
    };

    auto loadB = [&](int kt) {
        #pragma unroll
        for (int pi = 0; pi < 8; pi++) {
            int p  = pi * 256 + t;            // 0..2047
            int L  = p & 31;
            int nt = (p >> 5) & 15;
            int ks = p >> 9;
            int gg = L >> 2, tg = L & 3;
            int od = nt * 8 + gg;
            int k  = kt * 32 + ks * 8 + tg;
            const float* q = wb + (size_t)od * KDIM + k;
            rb[pi][0] = q[0];
            rb[pi][1] = q[4];
        }
    };

    auto stsAll = [&]() {
        #pragma unroll
        for (int qi = 0; qi < 4; qi++) {
            int q = qi * 256 + t;
            uint4 v;
            v.x = to_tf32(ra[qi][0]); v.y = to_tf32(ra[qi][1]);
            v.z = to_tf32(ra[qi][2]); v.w = to_tf32(ra[qi][3]);
            *(uint4*)&sA[q * 4] = v;
        }
        #pragma unroll
        for (int pi = 0; pi < 8; pi++) {
            int p = pi * 256 + t;
            uint2 v;
            v.x = to_tf32(rb[pi][0]); v.y = to_tf32(rb[pi][1]);
            *(uint2*)&sB[p * 2] = v;
        }
    };

    loadA(0); loadB(0);

    for (int kt = 0; kt < 13; kt++) {
        stsAll();
        __syncthreads();
        if (kt < 12) { loadA(kt + 1); loadB(kt + 1); }
        // compute this chunk from smem
        #pragma unroll
        for (int ks = 0; ks < 4; ks++) {
            uint4 af[2];
            #pragma unroll
            for (int tm = 0; tm < 2; tm++)
                af[tm] = *(const uint4*)&sA[((ks * 8 + (wm * 2 + tm)) * 32 + lane) * 4];
            uint2 bf[8];
            #pragma unroll
            for (int tn = 0; tn < 8; tn++)
                bf[tn] = *(const uint2*)&sB[((ks * 16 + (wnn * 8 + tn)) * 32 + lane) * 2];
            #pragma unroll
            for (int tm = 0; tm < 2; tm++)
                #pragma unroll
                for (int tn = 0; tn < 8; tn++)
                    MMA_TF32(acc[tm][tn], af[tm], bf[tn]);
        }
        __syncthreads();
    }

    // epilogue: c0=(g,2tig) c1=(g,2tig+1) c2=(g+8,2tig) c3=(g+8,2tig+1)
    #pragma unroll
    for (int tm = 0; tm < 2; tm++) {
        #pragma unroll
        for (int tn = 0; tn < 8; tn++) {
            int row0 = wm * 32 + tm * 16 + g;
            int col  = wnn * 64 + tn * 8 + 2 * tig;
            #pragma unroll
            for (int rr = 0; rr < 2; rr++) {
                int row = row0 + rr * 8;
                int hh = row >> 6, w = row & 63;
                float* ob = g_uhat +
                    ((((size_t)(ic * NB + nb) * HH + h0 + hh) * WWs + w) * ODIM + col);
                float2 v; v.x = acc[tm][tn][rr * 2]; v.y = acc[tm][tn][rr * 2 + 1];
                *(float2*)ob = v;
            }
        }
    }
}

// =================================================================================
// PV kernel (unchanged from passing version)
// =================================================================================
#define PVP 8
__global__ void __launch_bounds__(64) pv_kernel(float* __restrict__ out, int mode) {
    __shared__ float uh[NI * PVP * 132];
    __shared__ float rs[NI * NO * PVP];

    const int n = blockIdx.z, h = blockIdx.y, w0 = blockIdx.x * PVP;
    const int t = threadIdx.x;

    for (int i = 0; i < NI; i++) {
        const float4* src = (const float4*)(g_uhat +
            (((size_t)(i * NB + n) * HH + h) * WWs + w0) * ODIM);
        #pragma unroll
        for (int j = 0; j < 4; j++) {
            int idx = t + j * 64;
            int p = idx >> 5, q = idx & 31;
            *(float4*)&uh[(i * PVP + p) * 132 + q * 4] = src[idx];
        }
    }
    if (mode != 0) {
        int i = t >> 3, o = t & 7;
        const float* rb = g_r + ((size_t)(i * NB + n) * NO + o) * HWs + h * WWs + w0;
        #pragma unroll
        for (int p = 0; p < PVP; p++) rs[(i * NO + o) * PVP + p] = rb[p];
    }
    __syncthreads();

    const int o = t >> 3, p = t & 7;
    const int w = w0 + p;

    float r0 = 0.f;
    if (mode == 0) {
        int ch = min(h + 2, HH - 1) - max(h - 2, 0) + 1;
        int cw = min(w + 2, WWs - 1) - max(w - 2, 0) + 1;
        r0 = 1.f / (8.f * (float)(ch * cw));
    }

    unsigned long long pacc[8];
    #pragma unroll
    for (int d2 = 0; d2 < 8; d2++) pacc[d2] = 0ull;

    #pragma unroll
    for (int i = 0; i < NI; i++) {
        float rv = (mode == 0) ? r0 : rs[(i * NO + o) * PVP + p];
        unsigned long long rd = pk2(rv, rv);
        const unsigned long long* uq =
            (const unsigned long long*)&uh[(i * PVP + p) * 132 + o * 16];
        #pragma unroll
        for (int d2 = 0; d2 < 8; d2++) fma2(pacc[d2], uq[d2], rd);
    }

    float pv[16];
    #pragma unroll
    for (int d2 = 0; d2 < 8; d2++) upk2(pacc[d2], pv[2 * d2], pv[2 * d2 + 1]);

    float ns = 0.f;
    #pragma unroll
    for (int d = 0; d < 16; d++) ns += pv[d] * pv[d];
    float scale = ns / ((1.f + ns) * sqrtf(ns + 1e-9f));
    float v[16];
    #pragma unroll
    for (int d = 0; d < 16; d++) v[d] = pv[d] * scale;

    if (mode < 2) {
        unsigned long long vp[8];
        #pragma unroll
        for (int d2 = 0; d2 < 8; d2++) vp[d2] = pk2(v[2 * d2], v[2 * d2 + 1]);
        #pragma unroll
        for (int i = 0; i < NI; i++) {
            const unsigned long long* uq =
                (const unsigned long long*)&uh[(i * PVP + p) * 132 + o * 16];
            unsigned long long aa = 0ull;
            #pragma unroll
            for (int d2 = 0; d2 < 8; d2++) fma2(aa, uq[d2], vp[d2]);
            float alo, ahi; upk2(aa, alo, ahi);
            float a = alo + ahi;
            size_t bi = ((size_t)(i * NB + n) * NO + o) * HWs + h * WWs + w;
            g_b[bi] = (mode == 0) ? a : g_b[bi] + a;
        }
    } else {
        #pragma unroll
        for (int d = 0; d < 16; d++)
            out[(((size_t)n * NO + o) * DCAP + d) * HWs + h * WWs + w] = v[d];
    }
}

// =================================================================================
// R kernels (unchanged)
// =================================================================================
__global__ void rk1_kernel() {
    int idx = blockIdx.x * 256 + threadIdx.x;
    int in = idx >> 12, hw = idx & 4095;
    const float* bb = g_b + (size_t)in * NO * HWs + hw;
    float m = bb[0];
    #pragma unroll
    for (int o = 1; o < NO; o++) m = fmaxf(m, bb[(size_t)o * HWs]);
    g_t[idx] = m;
}

__global__ void rk2_kernel() {
    int idx = blockIdx.x * 256 + threadIdx.x;
    int in = idx >> 12, hw = idx & 4095, h = hw >> 6, w = hw & 63;
    const float* tb = g_t + (size_t)in * HWs;
    float m = -3.4e38f;
    #pragma unroll
    for (int dh = -2; dh <= 2; dh++) {
        int hh = h + dh;
        if ((unsigned)hh < HH) {
            #pragma unroll
            for (int dw = -2; dw <= 2; dw++) {
                int ww = w + dw;
                if ((unsigned)ww < WWs) m = fmaxf(m, tb[hh * WWs + ww]);
            }
        }
    }
    const float* bb = g_b + (size_t)in * NO * HWs + hw;
    float s = 0.f;
    #pragma unroll
    for (int o = 0; o < NO; o++) s += __expf(bb[(size_t)o * HWs] - m);
    g_bm[idx] = m;
    g_sc[idx] = s;
}

__global__ void rk3_kernel() {
    int idx = blockIdx.x * 256 + threadIdx.x;
    int in = idx >> 12, hw = idx & 4095, h = hw >> 6, w = hw & 63;
    const float* scb = g_sc + (size_t)in * HWs;
    float ss = 0.f;
    #pragma unroll
    for (int dh = -2; dh <= 2; dh++) {
        int hh = h + dh;
        if ((unsigned)hh < HH) {
            #pragma unroll
            for (int dw = -2; dw <= 2; dw++) {
                int ww = w + dw;
                if ((unsigned)ww < WWs) ss += scb[hh * WWs + ww];
            }
        }
    }
    float bm  = g_bm[idx];
    float inv = 1.f / ss;
    const float* bb = g_b + (size_t)in * NO * HWs + hw;
    float*       rr = g_r + (size_t)in * NO * HWs + hw;
    #pragma unroll
    for (int o = 0; o < NO; o++)
        rr[(size_t)o * HWs] = __expf(bb[(size_t)o * HWs] - bm) * inv;
}

// =================================================================================
extern "C" void kernel_launch(void* const* d_in, const int* in_sizes, int n_in,
                              void* d_out, int out_size) {
    const float* u  = (const float*)d_in[0];   // [8, 8, 16, 64, 64]
    const float* Wp = (const float*)d_in[1];   // [8, 128, 16, 5, 5]
    float* out = (float*)d_out;                // [8, 8, 16, 64, 64]

    trans_kernel<<<NB * NI, 256>>>(u);
    repack_kernel<<<NI * ODIM, 416>>>(Wp);
    conv_mma_kernel<<<dim3(HH / 2, NB, NI), 256>>>();

    // routing iteration 0 (b = 0 -> analytic r)
    pv_kernel<<<dim3(WWs / PVP, HH, NB), 64>>>(out, 0);

    // routing iterations 1, 2
    for (int it = 1; it <= 2; it++) {
        rk1_kernel<<<1024, 256>>>();
        rk2_kernel<<<1024, 256>>>();
        rk3_kernel<<<1024, 256>>>();
        pv_kernel<<<dim3(WWs / PVP, HH, NB), 64>>>(out, it);
    }
}

// round 7
// speedup vs baseline: 2.5568x; 1.2443x over previous
#include <cuda_runtime.h>
#include <cstdint>
#include <math.h>

#define NB   8      // batch
#define NI   8      // input capsules
#define CIN  16     // input capsule dim
#define HH   64
#define WWs  64
#define NO   8      // output capsules
#define DCAP 16     // output capsule dim
#define ODIM 128    // NO*DCAP
#define HWs  4096   // HH*WWs
#define KDIM 416    // 26 positions * 16 c (25 real + 1 zero pad)

// ---------------- device scratch (static: no runtime allocation) ----------------
__device__ float g_uhat[(size_t)NI * NB * HH * WWs * ODIM];   // [i][n][h][w][od]  134MB
__device__ float g_ut  [(size_t)NB * NI * HWs * CIN];         // [n][i][h][w][c] tf32-rounded
__device__ float g_w2  [(size_t)NI * ODIM * KDIM];            // [i][od][p*16+c] tf32-rounded
__device__ float g_b [(size_t)NI * NB * NO * HH * WWs];       // [i][n][o][h][w]    8MB
__device__ float g_r [(size_t)NI * NB * NO * HH * WWs];
__device__ float g_t [(size_t)NI * NB * HH * WWs];
__device__ float g_bm[(size_t)NI * NB * HH * WWs];
__device__ float g_sc[(size_t)NI * NB * HH * WWs];

// ---------------- f32x2 helpers (routing kernels) ----------------
__device__ __forceinline__ unsigned long long pk2(float lo, float hi) {
    unsigned long long r;
    asm("mov.b64 %0, {%1, %2};" : "=l"(r) : "r"(__float_as_uint(lo)), "r"(__float_as_uint(hi)));
    return r;
}
__device__ __forceinline__ void upk2(unsigned long long v, float& lo, float& hi) {
    unsigned int a, b;
    asm("mov.b64 {%0, %1}, %2;" : "=r"(a), "=r"(b) : "l"(v));
    lo = __uint_as_float(a); hi = __uint_as_float(b);
}
__device__ __forceinline__ void fma2(unsigned long long& d, unsigned long long a, unsigned long long b) {
    asm("fma.rn.f32x2 %0, %1, %2, %0;" : "+l"(d) : "l"(a), "l"(b));
}

__device__ __forceinline__ float to_tf32f(float f) {
    uint32_t r;
    asm("cvt.rna.tf32.f32 %0, %1;" : "=r"(r) : "f"(f));
    return __uint_as_float(r);
}

// =================================================================================
// Prep kernels (emit tf32-rounded values; conv consumes raw bits)
// =================================================================================
__global__ void __launch_bounds__(256) trans_kernel(const float* __restrict__ u) {
    __shared__ float s[16 * 65];
    const int t = threadIdx.x;
    const float* src = u + (size_t)blockIdx.x * CIN * HWs;   // blockIdx = n*NI+i
    float* dst = g_ut + (size_t)blockIdx.x * HWs * CIN;
    for (int h = 0; h < HH; h++) {
        #pragma unroll
        for (int j = 0; j < 4; j++) {
            int idx = t + j * 256;
            int c = idx >> 6, w = idx & 63;
            s[c * 65 + w] = to_tf32f(src[(size_t)c * HWs + h * WWs + w]);
        }
        __syncthreads();
        #pragma unroll
        for (int j = 0; j < 4; j++) {
            int idx = t + j * 256;
            int w = idx >> 4, c = idx & 15;
            dst[((size_t)h * WWs + w) * CIN + c] = s[c * 65 + w];
        }
        __syncthreads();
    }
}

__global__ void __launch_bounds__(416) repack_kernel(const float* __restrict__ Wp) {
    const int t = threadIdx.x;         // 0..415  (= p*16 + c)
    const int p = t >> 4, c = t & 15;
    float v = 0.f;
    if (p < 25) v = to_tf32f(Wp[((size_t)blockIdx.x * CIN + c) * 25 + p]);  // blockIdx = i*128+od
    g_w2[(size_t)blockIdx.x * KDIM + t] = v;
}

// =================================================================================
// Conv via mma.sync m16n8k8 tf32.
// CTA = (hp, n, i): M = 128 (rows h0,h0+1 x 64 w), N = 128 od, K = 400.
// A: per-CTA smem halo patch [6 rows][68 cols][16 c], pitch 20 (banks 20g+tig
//    all-distinct -> conflict-free). Fragments fetched directly from patch.
// B: 25 chunks of 16 k (one conv position each). Register prefetch (R4-proven
//    pattern) + fragment-major STS; fetch = conflict-free LDS.64.
// All smem STATIC (40.8KB): no cudaFuncSetAttribute, no dynamic smem, no cp.async.
// =================================================================================
#define PATCH_F  (408 * 20)            // 8160 floats = 32.6KB

#define MMA_TF32(d, a, b) \
    asm volatile("mma.sync.aligned.m16n8k8.row.col.f32.tf32.tf32.f32 " \
        "{%0,%1,%2,%3}, {%4,%5,%6,%7}, {%8,%9}, {%0,%1,%2,%3};" \
        : "+f"((d)[0]), "+f"((d)[1]), "+f"((d)[2]), "+f"((d)[3]) \
        : "r"((a).x), "r"((a).y), "r"((a).z), "r"((a).w), "r"((b).x), "r"((b).y))

__global__ void __launch_bounds__(256) conv_mma_kernel() {
    __shared__ float patch[PATCH_F];       // 32640 B
    __shared__ float sB[2048];             // 8192 B: one 16-k chunk, fragment-major

    const uint32_t* patchu = (const uint32_t*)patch;

    const int hp = blockIdx.x, nb = blockIdx.y, ic = blockIdx.z;
    const int h0 = hp * 2;
    const int t = threadIdx.x;
    const int lane = t & 31, wid = t >> 5;
    const int g = lane >> 2, tig = lane & 3;
    const int wm = wid & 3;        // 0..3 : m quarter (32 rows)
    const int wnn = wid >> 2;      // 0..1 : n half (64 cols)

    const float* ut = g_ut + (size_t)(nb * NI + ic) * HWs * CIN;
    const float* wb = g_w2 + (size_t)ic * ODIM * KDIM;

    // ---- stage input halo patch: rows h0-2..h0+3, cols -2..65, zero padded ----
    #pragma unroll
    for (int j = 0; j < 7; j++) {
        int idx = j * 256 + t;               // float4 index 0..1631
        if (idx < 1632) {
            int pixel = idx >> 2, q = idx & 3;
            int hl = pixel / 68, wcol = pixel - hl * 68;
            int h = h0 - 2 + hl, w = wcol - 2;
            float4 v = make_float4(0.f, 0.f, 0.f, 0.f);
            if ((unsigned)h < 64u && (unsigned)w < 64u)
                v = *(const float4*)(ut + ((size_t)h * WWs + w) * CIN + q * 4);
            *(float4*)&patch[pixel * 20 + q * 4] = v;
        }
    }

    float rb[4][2];   // prefetched B fragment values (4 pairs / thread / chunk)

    auto loadB = [&](int kt) {
        #pragma unroll
        for (int pi = 0; pi < 4; pi++) {
            int p  = pi * 256 + t;            // 0..1023
            int L  = p & 31;
            int nt = (p >> 5) & 15;           // n tile 0..15
            int ks = p >> 9;                  // 0..1
            int gg = L >> 2, tg = L & 3;
            int od = nt * 8 + gg;
            int k  = kt * 16 + ks * 8 + tg;
            const float* q = wb + (size_t)od * KDIM + k;
            rb[pi][0] = q[0];
            rb[pi][1] = q[4];
        }
    };

    auto stsB = [&]() {
        #pragma unroll
        for (int pi = 0; pi < 4; pi++) {
            int p = pi * 256 + t;
            float2 v; v.x = rb[pi][0]; v.y = rb[pi][1];
            *(float2*)&sB[p * 2] = v;
        }
    };

    loadB(0);

    float acc[2][8][4];
    #pragma unroll
    for (int a = 0; a < 2; a++)
        #pragma unroll
        for (int b = 0; b < 8; b++)
            #pragma unroll
            for (int c = 0; c < 4; c++) acc[a][b][c] = 0.f;

    const int hbase = (wm >> 1);                 // 0/1 : which h row
    const int wbase = (wm & 1) * 32 + g;         // + tm*16 later

    for (int kt = 0; kt < 25; kt++) {            // kt == conv position 0..24
        stsB();
        __syncthreads();
        if (kt < 24) loadB(kt + 1);

        int p5 = kt / 5;
        int dh = p5 - 2, dw = kt - p5 * 5 - 2;
        int prow = (hbase + dh + 2) * 68 + wbase + dw + 2;

        #pragma unroll
        for (int ks = 0; ks < 2; ks++) {
            int cb = ks * 8 + tig;
            uint4 af[2];
            #pragma unroll
            for (int tm = 0; tm < 2; tm++) {
                int px = prow + tm * 16;
                af[tm].x = patchu[px * 20 + cb];
                af[tm].y = patchu[(px + 8) * 20 + cb];
                af[tm].z = patchu[px * 20 + cb + 4];
                af[tm].w = patchu[(px + 8) * 20 + cb + 4];
            }
            uint2 bf[8];
            #pragma unroll
            for (int tn = 0; tn < 8; tn++)
                bf[tn] = *(const uint2*)&sB[((ks * 16 + wnn * 8 + tn) * 32 + lane) * 2];
            #pragma unroll
            for (int tm = 0; tm < 2; tm++)
                #pragma unroll
                for (int tn = 0; tn < 8; tn++)
                    MMA_TF32(acc[tm][tn], af[tm], bf[tn]);
        }
        __syncthreads();
    }

    // epilogue: c0=(g,2tig) c1=(g,2tig+1) c2=(g+8,2tig) c3=(g+8,2tig+1)
    #pragma unroll
    for (int tm = 0; tm < 2; tm++) {
        #pragma unroll
        for (int tn = 0; tn < 8; tn++) {
            int row0 = wm * 32 + tm * 16 + g;
            int col  = wnn * 64 + tn * 8 + 2 * tig;
            #pragma unroll
            for (int rr = 0; rr < 2; rr++) {
                int row = row0 + rr * 8;
                int hh = row >> 6, w = row & 63;
                float* ob = g_uhat +
                    ((((size_t)(ic * NB + nb) * HH + h0 + hh) * WWs + w) * ODIM + col);
                float2 v; v.x = acc[tm][tn][rr * 2]; v.y = acc[tm][tn][rr * 2 + 1];
                *(float2*)ob = v;
            }
        }
    }
}

// =================================================================================
// PV kernel (unchanged from passing version)
// =================================================================================
#define PVP 8
__global__ void __launch_bounds__(64) pv_kernel(float* __restrict__ out, int mode) {
    __shared__ float uh[NI * PVP * 132];
    __shared__ float rs[NI * NO * PVP];

    const int n = blockIdx.z, h = blockIdx.y, w0 = blockIdx.x * PVP;
    const int t = threadIdx.x;

    for (int i = 0; i < NI; i++) {
        const float4* src = (const float4*)(g_uhat +
            (((size_t)(i * NB + n) * HH + h) * WWs + w0) * ODIM);
        #pragma unroll
        for (int j = 0; j < 4; j++) {
            int idx = t + j * 64;
            int p = idx >> 5, q = idx & 31;
            *(float4*)&uh[(i * PVP + p) * 132 + q * 4] = src[idx];
        }
    }
    if (mode != 0) {
        int i = t >> 3, o = t & 7;
        const float* rb = g_r + ((size_t)(i * NB + n) * NO + o) * HWs + h * WWs + w0;
        #pragma unroll
        for (int p = 0; p < PVP; p++) rs[(i * NO + o) * PVP + p] = rb[p];
    }
    __syncthreads();

    const int o = t >> 3, p = t & 7;
    const int w = w0 + p;

    float r0 = 0.f;
    if (mode == 0) {
        int ch = min(h + 2, HH - 1) - max(h - 2, 0) + 1;
        int cw = min(w + 2, WWs - 1) - max(w - 2, 0) + 1;
        r0 = 1.f / (8.f * (float)(ch * cw));
    }

    unsigned long long pacc[8];
    #pragma unroll
    for (int d2 = 0; d2 < 8; d2++) pacc[d2] = 0ull;

    #pragma unroll
    for (int i = 0; i < NI; i++) {
        float rv = (mode == 0) ? r0 : rs[(i * NO + o) * PVP + p];
        unsigned long long rd = pk2(rv, rv);
        const unsigned long long* uq =
            (const unsigned long long*)&uh[(i * PVP + p) * 132 + o * 16];
        #pragma unroll
        for (int d2 = 0; d2 < 8; d2++) fma2(pacc[d2], uq[d2], rd);
    }

    float pv[16];
    #pragma unroll
    for (int d2 = 0; d2 < 8; d2++) upk2(pacc[d2], pv[2 * d2], pv[2 * d2 + 1]);

    float ns = 0.f;
    #pragma unroll
    for (int d = 0; d < 16; d++) ns += pv[d] * pv[d];
    float scale = ns / ((1.f + ns) * sqrtf(ns + 1e-9f));
    float v[16];
    #pragma unroll
    for (int d = 0; d < 16; d++) v[d] = pv[d] * scale;

    if (mode < 2) {
        unsigned long long vp[8];
        #pragma unroll
        for (int d2 = 0; d2 < 8; d2++) vp[d2] = pk2(v[2 * d2], v[2 * d2 + 1]);
        #pragma unroll
        for (int i = 0; i < NI; i++) {
            const unsigned long long* uq =
                (const unsigned long long*)&uh[(i * PVP + p) * 132 + o * 16];
            unsigned long long aa = 0ull;
            #pragma unroll
            for (int d2 = 0; d2 < 8; d2++) fma2(aa, uq[d2], vp[d2]);
            float alo, ahi; upk2(aa, alo, ahi);
            float a = alo + ahi;
            size_t bi = ((size_t)(i * NB + n) * NO + o) * HWs + h * WWs + w;
            g_b[bi] = (mode == 0) ? a : g_b[bi] + a;
        }
    } else {
        #pragma unroll
        for (int d = 0; d < 16; d++)
            out[(((size_t)n * NO + o) * DCAP + d) * HWs + h * WWs + w] = v[d];
    }
}

// =================================================================================
// R kernels (unchanged)
// =================================================================================
__global__ void rk1_kernel() {
    int idx = blockIdx.x * 256 + threadIdx.x;
    int in = idx >> 12, hw = idx & 4095;
    const float* bb = g_b + (size_t)in * NO * HWs + hw;
    float m = bb[0];
    #pragma unroll
    for (int o = 1; o < NO; o++) m = fmaxf(m, bb[(size_t)o * HWs]);
    g_t[idx] = m;
}

__global__ void rk2_kernel() {
    int idx = blockIdx.x * 256 + threadIdx.x;
    int in = idx >> 12, hw = idx & 4095, h = hw >> 6, w = hw & 63;
    const float* tb = g_t + (size_t)in * HWs;
    float m = -3.4e38f;
    #pragma unroll
    for (int dh = -2; dh <= 2; dh++) {
        int hh = h + dh;
        if ((unsigned)hh < HH) {
            #pragma unroll
            for (int dw = -2; dw <= 2; dw++) {
                int ww = w + dw;
                if ((unsigned)ww < WWs) m = fmaxf(m, tb[hh * WWs + ww]);
            }
        }
    }
    const float* bb = g_b + (size_t)in * NO * HWs + hw;
    float s = 0.f;
    #pragma unroll
    for (int o = 0; o < NO; o++) s += __expf(bb[(size_t)o * HWs] - m);
    g_bm[idx] = m;
    g_sc[idx] = s;
}

__global__ void rk3_kernel() {
    int idx = blockIdx.x * 256 + threadIdx.x;
    int in = idx >> 12, hw = idx & 4095, h = hw >> 6, w = hw & 63;
    const float* scb = g_sc + (size_t)in * HWs;
    float ss = 0.f;
    #pragma unroll
    for (int dh = -2; dh <= 2; dh++) {
        int hh = h + dh;
        if ((unsigned)hh < HH) {
            #pragma unroll
            for (int dw = -2; dw <= 2; dw++) {
                int ww = w + dw;
                if ((unsigned)ww < WWs) ss += scb[hh * WWs + ww];
            }
        }
    }
    float bm  = g_bm[idx];
    float inv = 1.f / ss;
    const float* bb = g_b + (size_t)in * NO * HWs + hw;
    float*       rr = g_r + (size_t)in * NO * HWs + hw;
    #pragma unroll
    for (int o = 0; o < NO; o++)
        rr[(size_t)o * HWs] = __expf(bb[(size_t)o * HWs] - bm) * inv;
}

// =================================================================================
extern "C" void kernel_launch(void* const* d_in, const int* in_sizes, int n_in,
                              void* d_out, int out_size) {
    const float* u  = (const float*)d_in[0];   // [8, 8, 16, 64, 64]
    const float* Wp = (const float*)d_in[1];   // [8, 128, 16, 5, 5]
    float* out = (float*)d_out;                // [8, 8, 16, 64, 64]

    trans_kernel<<<NB * NI, 256>>>(u);
    repack_kernel<<<NI * ODIM, 416>>>(Wp);
    conv_mma_kernel<<<dim3(HH / 2, NB, NI), 256>>>();

    // routing iteration 0 (b = 0 -> analytic r)
    pv_kernel<<<dim3(WWs / PVP, HH, NB), 64>>>(out, 0);

    // routing iterations 1, 2
    for (int it = 1; it <= 2; it++) {
        rk1_kernel<<<1024, 256>>>();
        rk2_kernel<<<1024, 256>>>();
        rk3_kernel<<<1024, 256>>>();
        pv_kernel<<<dim3(WWs / PVP, HH, NB), 64>>>(out, it);
    }
}

// round 10
// speedup vs baseline: 2.6681x; 1.0435x over previous
#include <cuda_runtime.h>
#include <cstdint>
#include <math.h>

#define NB   8      // batch
#define NI   8      // input capsules
#define CIN  16     // input capsule dim
#define HH   64
#define WWs  64
#define NO   8      // output capsules
#define DCAP 16     // output capsule dim
#define ODIM 128    // NO*DCAP
#define HWs  4096   // HH*WWs
#define KDIM 416    // 26 positions * 16 c (25 real + 1 zero pad)

// ---------------- device scratch (static: no runtime allocation) ----------------
__device__ float g_uhat[(size_t)NI * NB * HH * WWs * ODIM];   // [i][n][h][w][od]  134MB
__device__ float g_ut  [(size_t)NB * NI * HWs * CIN];         // [n][i][h][w][c] tf32-rounded
__device__ float g_w2  [(size_t)NI * ODIM * KDIM];            // [i][od][p*16+c] tf32-rounded
__device__ float g_b [(size_t)NI * NB * NO * HH * WWs];       // [i][n][o][h][w]    8MB
__device__ float g_r [(size_t)NI * NB * NO * HH * WWs];
__device__ float g_t [(size_t)NI * NB * HH * WWs];
__device__ float g_bm[(size_t)NI * NB * HH * WWs];
__device__ float g_sc[(size_t)NI * NB * HH * WWs];

__device__ __forceinline__ float to_tf32f(float f) {
    uint32_t r;
    asm("cvt.rna.tf32.f32 %0, %1;" : "=r"(r) : "f"(f));
    return __uint_as_float(r);
}

// =================================================================================
// Prep kernels (emit tf32-rounded values; conv consumes raw bits)
// =================================================================================
__global__ void __launch_bounds__(256) trans_kernel(const float* __restrict__ u) {
    __shared__ float s[16 * 65];
    const int t = threadIdx.x;
    const float* src = u + (size_t)blockIdx.x * CIN * HWs;   // blockIdx = n*NI+i
    float* dst = g_ut + (size_t)blockIdx.x * HWs * CIN;
    for (int h = 0; h < HH; h++) {
        #pragma unroll
        for (int j = 0; j < 4; j++) {
            int idx = t + j * 256;
            int c = idx >> 6, w = idx & 63;
            s[c * 65 + w] = to_tf32f(src[(size_t)c * HWs + h * WWs + w]);
        }
        __syncthreads();
        #pragma unroll
        for (int j = 0; j < 4; j++) {
            int idx = t + j * 256;
            int w = idx >> 4, c = idx & 15;
            dst[((size_t)h * WWs + w) * CIN + c] = s[c * 65 + w];
        }
        __syncthreads();
    }
}

__global__ void __launch_bounds__(416) repack_kernel(const float* __restrict__ Wp) {
    const int t = threadIdx.x;         // 0..415  (= p*16 + c)
    const int p = t >> 4, c = t & 15;
    float v = 0.f;
    if (p < 25) v = to_tf32f(Wp[((size_t)blockIdx.x * CIN + c) * 25 + p]);  // blockIdx = i*128+od
    g_w2[(size_t)blockIdx.x * KDIM + t] = v;
}

// =================================================================================
// Conv via mma.sync m16n8k8 tf32.
// CTA = (hp, n, i): M = 128 (rows h0,h0+1 x 64 w), N = 128 od, K = 400.
// A: per-CTA smem halo patch, pitch 20 (conflict-free for the (g,tig) lane grid).
// B: 25 chunks of 16 k (one conv position each), DOUBLE-buffered fragment-major
//    smem, one __syncthreads per chunk, LDG issued 2 chunks ahead.
// Static smem 49024 B (< 48KB limit); __launch_bounds__(256,2) -> 2 CTAs/SM.
// =================================================================================
#define PATCH_F  (408 * 20)            // 8160 floats = 32640 B

#define MMA_TF32(d, a, b) \
    asm volatile("mma.sync.aligned.m16n8k8.row.col.f32.tf32.tf32.f32 " \
        "{%0,%1,%2,%3}, {%4,%5,%6,%7}, {%8,%9}, {%0,%1,%2,%3};" \
        : "+f"((d)[0]), "+f"((d)[1]), "+f"((d)[2]), "+f"((d)[3]) \
        : "r"((a).x), "r"((a).y), "r"((a).z), "r"((a).w), "r"((b).x), "r"((b).y))

__global__ void __launch_bounds__(256, 2) conv_mma_kernel() {
    __shared__ float patch[PATCH_F];       // 32640 B
    __shared__ float sB[2][2048];          // 2 x 8192 B: 16-k chunks, fragment-major

    const uint32_t* patchu = (const uint32_t*)patch;

    const int hp = blockIdx.x, nb = blockIdx.y, ic = blockIdx.z;
    const int h0 = hp * 2;
    const int t = threadIdx.x;
    const int lane = t & 31, wid = t >> 5;
    const int g = lane >> 2, tig = lane & 3;
    const int wm = wid & 3;        // 0..3 : m quarter (32 rows)
    const int wnn = wid >> 2;      // 0..1 : n half (64 cols)

    const float* ut = g_ut + (size_t)(nb * NI + ic) * HWs * CIN;
    const float* wb = g_w2 + (size_t)ic * ODIM * KDIM;

    // ---- stage input halo patch: rows h0-2..h0+3, cols -2..65, zero padded ----
    #pragma unroll
    for (int j = 0; j < 7; j++) {
        int idx = j * 256 + t;               // float4 index 0..1631
        if (idx < 1632) {
            int pixel = idx >> 2, q = idx & 3;
            int hl = pixel / 68, wcol = pixel - hl * 68;
            int h = h0 - 2 + hl, w = wcol - 2;
            float4 v = make_float4(0.f, 0.f, 0.f, 0.f);
            if ((unsigned)h < 64u && (unsigned)w < 64u)
                v = *(const float4*)(ut + ((size_t)h * WWs + w) * CIN + q * 4);
            *(float4*)&patch[pixel * 20 + q * 4] = v;
        }
    }

    float rb[4][2];   // prefetched B fragment values (4 pairs / thread / chunk)

    auto loadB = [&](int kt) {
        #pragma unroll
        for (int pi = 0; pi < 4; pi++) {
            int p  = pi * 256 + t;            // 0..1023
            int L  = p & 31;
            int nt = (p >> 5) & 15;           // n tile 0..15
            int ks = p >> 9;                  // 0..1
            int gg = L >> 2, tg = L & 3;
            int od = nt * 8 + gg;
            int k  = kt * 16 + ks * 8 + tg;
            const float* q = wb + (size_t)od * KDIM + k;
            rb[pi][0] = q[0];
            rb[pi][1] = q[4];
        }
    };

    auto stsB = [&](int buf) {
        #pragma unroll
        for (int pi = 0; pi < 4; pi++) {
            int p = pi * 256 + t;
            float2 v; v.x = rb[pi][0]; v.y = rb[pi][1];
            *(float2*)&sB[buf][p * 2] = v;
        }
    };

    loadB(0);
    stsB(0);
    __syncthreads();        // patch + chunk 0 visible
    loadB(1);

    float acc[2][8][4];
    #pragma unroll
    for (int a = 0; a < 2; a++)
        #pragma unroll
        for (int b = 0; b < 8; b++)
            #pragma unroll
            for (int c = 0; c < 4; c++) acc[a][b][c] = 0.f;

    const int hbase = (wm >> 1);                 // 0/1 : which h row
    const int wbase = (wm & 1) * 32 + g;         // + tm*16 later

    int buf = 0;
    for (int kt = 0; kt < 25; kt++) {            // kt == conv position 0..24
        int p5 = kt / 5;
        int dh = p5 - 2, dw = kt - p5 * 5 - 2;
        int prow = (hbase + dh + 2) * 68 + wbase + dw + 2;

        #pragma unroll
        for (int ks = 0; ks < 2; ks++) {
            int cb = ks * 8 + tig;
            uint4 af[2];
            #pragma unroll
            for (int tm = 0; tm < 2; tm++) {
                int px = prow + tm * 16;
                af[tm].x = patchu[px * 20 + cb];
                af[tm].y = patchu[(px + 8) * 20 + cb];
                af[tm].z = patchu[px * 20 + cb + 4];
                af[tm].w = patchu[(px + 8) * 20 + cb + 4];
            }
            uint2 bf[8];
            #pragma unroll
            for (int tn = 0; tn < 8; tn++)
                bf[tn] = *(const uint2*)&sB[buf][((ks * 16 + wnn * 8 + tn) * 32 + lane) * 2];
            #pragma unroll
            for (int tm = 0; tm < 2; tm++)
                #pragma unroll
                for (int tn = 0; tn < 8; tn++)
                    MMA_TF32(acc[tm][tn], af[tm], bf[tn]);
        }

        if (kt < 24) {
            stsB(buf ^ 1);                       // chunk kt+1 (regs -> smem)
            __syncthreads();
            if (kt < 23) loadB(kt + 2);          // overlaps next chunk's mma
            buf ^= 1;
        }
    }

    // epilogue: c0=(g,2tig) c1=(g,2tig+1) c2=(g+8,2tig) c3=(g+8,2tig+1)
    #pragma unroll
    for (int tm = 0; tm < 2; tm++) {
        #pragma unroll
        for (int tn = 0; tn < 8; tn++) {
            int row0 = wm * 32 + tm * 16 + g;
            int col  = wnn * 64 + tn * 8 + 2 * tig;
            #pragma unroll
            for (int rr = 0; rr < 2; rr++) {
                int row = row0 + rr * 8;
                int hh = row >> 6, w = row & 63;
                float* ob = g_uhat +
                    ((((size_t)(ic * NB + nb) * HH + h0 + hh) * WWs + w) * ODIM + col);
                float2 v; v.x = acc[tm][tn][rr * 2]; v.y = acc[tm][tn][rr * 2 + 1];
                *(float2*)ob = v;
            }
        }
    }
}

// =================================================================================
// pvb: b-update iterations via Gram trick. Thread = (pixel, o); NO smem.
//   G_ij = uh_i . uh_j (16-d), s_i = sum_j r_j G_ij, ns = |p|^2 = sum_i r_i s_i,
//   agree_i = scale * s_i  with scale = ns / ((1+ns) sqrt(ns+1e-9)).
// mode 0: analytic r (b=0), b = agree;  mode 1: load r, b += agree.
// =================================================================================
__global__ void __launch_bounds__(256) pvb_kernel(int mode) {
    const int t = threadIdx.x;
    const int o = t & 7, p = t >> 3;            // 32 pixels x 8 o per block
    const int P = blockIdx.x * 32 + p;          // global pixel in [0, NB*HWs)
    const int n = P >> 12, hw = P & 4095;

    float r[8];
    if (mode == 0) {
        int h = hw >> 6, w = hw & 63;
        int ch = min(h + 2, HH - 1) - max(h - 2, 0) + 1;
        int cw = min(w + 2, WWs - 1) - max(w - 2, 0) + 1;
        float r0 = 1.f / (8.f * (float)(ch * cw));
        #pragma unroll
        for (int j = 0; j < 8; j++) r[j] = r0;
    } else {
        #pragma unroll
        for (int j = 0; j < 8; j++)
            r[j] = g_r[((size_t)(j * NB + n) * NO + o) * HWs + hw];
    }

    float G[36];
    #pragma unroll
    for (int k = 0; k < 36; k++) G[k] = 0.f;

    const size_t ubase = ((size_t)n * HWs + hw) * ODIM + o * 16;
    #pragma unroll
    for (int d4 = 0; d4 < 4; d4++) {
        float4 u[8];
        #pragma unroll
        for (int i = 0; i < 8; i++)
            u[i] = *(const float4*)(g_uhat + ubase + (size_t)i * NB * HWs * ODIM + d4 * 4);
        int idx = 0;
        #pragma unroll
        for (int i = 0; i < 8; i++)
            #pragma unroll
            for (int j = i; j < 8; j++, idx++)
                G[idx] += u[i].x * u[j].x + u[i].y * u[j].y
                        + u[i].z * u[j].z + u[i].w * u[j].w;
    }

    float s[8];
    #pragma unroll
    for (int i = 0; i < 8; i++) s[i] = 0.f;
    {
        int idx = 0;
        #pragma unroll
        for (int i = 0; i < 8; i++)
            #pragma unroll
            for (int j = i; j < 8; j++, idx++) {
                s[i] += r[j] * G[idx];
                if (j > i) s[j] += r[i] * G[idx];
            }
    }
    float ns = 0.f;
    #pragma unroll
    for (int i = 0; i < 8; i++) ns += r[i] * s[i];
    float scale = ns / ((1.f + ns) * sqrtf(ns + 1e-9f));

    #pragma unroll
    for (int i = 0; i < 8; i++) {
        size_t bi = ((size_t)(i * NB + n) * NO + o) * HWs + hw;
        float a = scale * s[i];
        g_b[bi] = (mode == 0) ? a : g_b[bi] + a;
    }
}

// =================================================================================
// pvout: final iteration — stream p, squash, write v to output. NO smem.
// =================================================================================
__global__ void __launch_bounds__(256) pvout_kernel(float* __restrict__ out) {
    const int t = threadIdx.x;
    const int o = t & 7, p = t >> 3;
    const int P = blockIdx.x * 32 + p;
    const int n = P >> 12, hw = P & 4095;

    float r[8];
    #pragma unroll
    for (int j = 0; j < 8; j++)
        r[j] = g_r[((size_t)(j * NB + n) * NO + o) * HWs + hw];

    float pv[16];
    #pragma unroll
    for (int d = 0; d < 16; d++) pv[d] = 0.f;

    const size_t ubase = ((size_t)n * HWs + hw) * ODIM + o * 16;
    #pragma unroll
    for (int d4 = 0; d4 < 4; d4++) {
        #pragma unroll
        for (int i = 0; i < 8; i++) {
            float4 u = *(const float4*)(g_uhat + ubase + (size_t)i * NB * HWs * ODIM + d4 * 4);
            pv[d4 * 4 + 0] += r[i] * u.x;
            pv[d4 * 4 + 1] += r[i] * u.y;
            pv[d4 * 4 + 2] += r[i] * u.z;
            pv[d4 * 4 + 3] += r[i] * u.w;
        }
    }

    float ns = 0.f;
    #pragma unroll
    for (int d = 0; d < 16; d++) ns += pv[d] * pv[d];
    float scale = ns / ((1.f + ns) * sqrtf(ns + 1e-9f));

    #pragma unroll
    for (int d = 0; d < 16; d++)
        out[(((size_t)n * NO + o) * DCAP + d) * HWs + hw] = pv[d] * scale;
}

// =================================================================================
// R kernels (unchanged)
// =================================================================================
__global__ void rk1_kernel() {
    int idx = blockIdx.x * 256 + threadIdx.x;
    int in = idx >> 12, hw = idx & 4095;
    const float* bb = g_b + (size_t)in * NO * HWs + hw;
    float m = bb[0];
    #pragma unroll
    for (int o = 1; o < NO; o++) m = fmaxf(m, bb[(size_t)o * HWs]);
    g_t[idx] = m;
}

__global__ void rk2_kernel() {
    int idx = blockIdx.x * 256 + threadIdx.x;
    int in = idx >> 12, hw = idx & 4095, h = hw >> 6, w = hw & 63;
    const float* tb = g_t + (size_t)in * HWs;
    float m = -3.4e38f;
    #pragma unroll
    for (int dh = -2; dh <= 2; dh++) {
        int hh = h + dh;
        if ((unsigned)hh < HH) {
            #pragma unroll
            for (int dw = -2; dw <= 2; dw++) {
                int ww = w + dw;
                if ((unsigned)ww < WWs) m = fmaxf(m, tb[hh * WWs + ww]);
            }
        }
    }
    const float* bb = g_b + (size_t)in * NO * HWs + hw;
    float s = 0.f;
    #pragma unroll
    for (int o = 0; o < NO; o++) s += __expf(bb[(size_t)o * HWs] - m);
    g_bm[idx] = m;
    g_sc[idx] = s;
}

__global__ void rk3_kernel() {
    int idx = blockIdx.x * 256 + threadIdx.x;
    int in = idx >> 12, hw = idx & 4095, h = hw >> 6, w = hw & 63;
    const float* scb = g_sc + (size_t)in * HWs;
    float ss = 0.f;
    #pragma unroll
    for (int dh = -2; dh <= 2; dh++) {
        int hh = h + dh;
        if ((unsigned)hh < HH) {
            #pragma unroll
            for (int dw = -2; dw <= 2; dw++) {
                int ww = w + dw;
                if ((unsigned)ww < WWs) ss += scb[hh * WWs + ww];
            }
        }
    }
    float bm  = g_bm[idx];
    float inv = 1.f / ss;
    const float* bb = g_b + (size_t)in * NO * HWs + hw;
    float*       rr = g_r + (size_t)in * NO * HWs + hw;
    #pragma unroll
    for (int o = 0; o < NO; o++)
        rr[(size_t)o * HWs] = __expf(bb[(size_t)o * HWs] - bm) * inv;
}

// =================================================================================
extern "C" void kernel_launch(void* const* d_in, const int* in_sizes, int n_in,
                              void* d_out, int out_size) {
    const float* u  = (const float*)d_in[0];   // [8, 8, 16, 64, 64]
    const float* Wp = (const float*)d_in[1];   // [8, 128, 16, 5, 5]
    float* out = (float*)d_out;                // [8, 8, 16, 64, 64]

    trans_kernel<<<NB * NI, 256>>>(u);
    repack_kernel<<<NI * ODIM, 416>>>(Wp);
    conv_mma_kernel<<<dim3(HH / 2, NB, NI), 256>>>();

    // routing iteration 0 (b = 0 -> analytic r)
    pvb_kernel<<<NB * HWs / 32, 256>>>(0);

    // routing iteration 1
    rk1_kernel<<<1024, 256>>>();
    rk2_kernel<<<1024, 256>>>();
    rk3_kernel<<<1024, 256>>>();
    pvb_kernel<<<NB * HWs / 32, 256>>>(1);

    // routing iteration 2 (final output)
    rk1_kernel<<<1024, 256>>>();
    rk2_kernel<<<1024, 256>>>();
    rk3_kernel<<<1024, 256>>>();
    pvout_kernel<<<NB * HWs / 32, 256>>>(out);
}

// round 12
// speedup vs baseline: 5.7032x; 2.1375x over previous
#include <cuda_runtime.h>
#include <cuda_fp16.h>
#include <cstdint>
#include <math.h>

#define NB   8      // batch
#define NI   8      // input capsules
#define CIN  16     // input capsule dim
#define HH   64
#define WWs  64
#define NO   8      // output capsules
#define DCAP 16     // output capsule dim
#define ODIM 128    // NO*DCAP
#define HWs  4096   // HH*WWs

// ---------------- device scratch (static: no runtime allocation) ----------------
__device__ __half g_uhat[(size_t)NI * NB * HWs * ODIM];   // [i][n][hw][od]  67MB fp16
__device__ __half g_uth [(size_t)NB * NI * HWs * CIN];    // [n][i][hw][c]   16.8MB fp16
__device__ uint2  g_w2f [(size_t)NI * 25 * 512];          // [i][pos][od*4+j] {b0,b1}
__device__ float g_b [(size_t)NI * NB * NO * HWs];        // [i][n][o][hw]   8MB
__device__ float g_r [(size_t)NI * NB * NO * HWs];
__device__ float g_t [(size_t)NI * NB * HWs];
__device__ float g_bm[(size_t)NI * NB * HWs];
__device__ float g_sc[(size_t)NI * NB * HWs];

__device__ __forceinline__ uint32_t pack_h2(float lo, float hi) {
    __half2 h = __floats2half2_rn(lo, hi);
    return *(uint32_t*)&h;
}

// =================================================================================
// Prep: transpose u to [n][i][hw][c] fp16
// =================================================================================
__global__ void __launch_bounds__(256) trans_kernel(const float* __restrict__ u) {
    __shared__ float s[16 * 65];
    const int t = threadIdx.x;
    const float* src = u + (size_t)blockIdx.x * CIN * HWs;   // blockIdx = n*NI+i
    __half* dst = g_uth + (size_t)blockIdx.x * HWs * CIN;
    for (int h = 0; h < HH; h++) {
        #pragma unroll
        for (int j = 0; j < 4; j++) {
            int idx = t + j * 256;
            int c = idx >> 6, w = idx & 63;
            s[c * 65 + w] = src[(size_t)c * HWs + h * WWs + w];
        }
        __syncthreads();
        #pragma unroll
        for (int j = 0; j < 2; j++) {
            int idx = t + j * 256;          // 0..511 = 64 w x 8 cpair
            int w = idx >> 3, cp = idx & 7;
            uint32_t v = pack_h2(s[(2 * cp) * 65 + w], s[(2 * cp + 1) * 65 + w]);
            *(uint32_t*)(dst + ((size_t)h * WWs + w) * CIN + cp * 2) = v;
        }
        __syncthreads();
    }
}

// =================================================================================
// Prep: repack W into fp16 B-fragment order.
// g_w2f[(i*25+pos)*512 + od*4 + j] = { pack(W[od][2j],W[od][2j+1]),
//                                      pack(W[od][2j+8],W[od][2j+9]) }  (c within pos)
// =================================================================================
__global__ void __launch_bounds__(512) repack_kernel(const float* __restrict__ Wp) {
    const int i = blockIdx.x / 25, pos = blockIdx.x - i * 25;
    const int t = threadIdx.x;                // 0..511
    const int od = t >> 2, j = t & 3;
    // Wp layout: [i][od(128)][c(16)][25]
    const float* base = Wp + (((size_t)(i * 128 + od)) * 16) * 25 + pos;
    float c0 = base[(2 * j) * 25],     c1 = base[(2 * j + 1) * 25];
    float c2 = base[(2 * j + 8) * 25], c3 = base[(2 * j + 9) * 25];
    uint2 v; v.x = pack_h2(c0, c1); v.y = pack_h2(c2, c3);
    g_w2f[(size_t)blockIdx.x * 512 + t] = v;
}

// =================================================================================
// Conv via mma.sync m16n8k16 fp16 (fp32 accumulate).
// CTA = (hp, n, i): M = 128 (rows h0,h0+1 x 64 w), N = 128 od, K = 400.
// One chunk = one conv position (k16 = the 16 c's). A: fp16 halo patch, pitch 24
// halves (banks 12g+tig all-distinct). B: fragment-packed uint2, double-buffered.
// =================================================================================
#define PPITCH 24
#define PATCH_H (408 * PPITCH)   // 9792 halves = 19584 B

#define MMA_F16(d, a0, a1, a2, a3, b) \
    asm volatile("mma.sync.aligned.m16n8k16.row.col.f32.f16.f16.f32 " \
        "{%0,%1,%2,%3}, {%4,%5,%6,%7}, {%8,%9}, {%0,%1,%2,%3};" \
        : "+f"((d)[0]), "+f"((d)[1]), "+f"((d)[2]), "+f"((d)[3]) \
        : "r"(a0), "r"(a1), "r"(a2), "r"(a3), "r"((b).x), "r"((b).y))

__global__ void __launch_bounds__(256, 2) conv_mma_kernel() {
    __shared__ __align__(16) __half patch[PATCH_H];   // 19584 B
    __shared__ uint2 sB[2][512];                      // 2 x 4096 B

    const int hp = blockIdx.x, nb = blockIdx.y, ic = blockIdx.z;
    const int h0 = hp * 2;
    const int t = threadIdx.x;
    const int lane = t & 31, wid = t >> 5;
    const int g = lane >> 2, tig = lane & 3;
    const int wm = wid & 3;        // 0..3 : m quarter (32 rows)
    const int wnn = wid >> 2;      // 0..1 : n half (64 cols)

    const __half* uth = g_uth + (size_t)(nb * NI + ic) * HWs * CIN;
    const uint2* wf = g_w2f + (size_t)ic * 25 * 512;

    // ---- stage halo patch: rows h0-2..h0+3, cols -2..65, zero padded ----
    #pragma unroll
    for (int j = 0; j < 4; j++) {
        int idx = j * 256 + t;               // uint4 item 0..815 (408 px x 2)
        if (idx < 816) {
            int pixel = idx >> 1, half8 = idx & 1;
            int hl = pixel / 68, wcol = pixel - hl * 68;
            int h = h0 - 2 + hl, w = wcol - 2;
            uint4 v = make_uint4(0u, 0u, 0u, 0u);
            if ((unsigned)h < 64u && (unsigned)w < 64u)
                v = *(const uint4*)(uth + ((size_t)h * WWs + w) * CIN + half8 * 8);
            *(uint4*)&patch[pixel * PPITCH + half8 * 8] = v;
        }
    }

    uint2 rbv[2];
    auto loadB = [&](int kt) {
        const uint2* src = wf + (size_t)kt * 512;
        rbv[0] = src[t];
        rbv[1] = src[t + 256];
    };
    auto stsB = [&](int buf) {
        sB[buf][t] = rbv[0];
        sB[buf][t + 256] = rbv[1];
    };

    loadB(0);
    stsB(0);
    __syncthreads();        // patch + chunk 0 visible
    loadB(1);

    float acc[2][8][4];
    #pragma unroll
    for (int a = 0; a < 2; a++)
        #pragma unroll
        for (int b = 0; b < 8; b++)
            #pragma unroll
            for (int c = 0; c < 4; c++) acc[a][b][c] = 0.f;

    const int hbase = (wm >> 1);
    const int wbase = (wm & 1) * 32 + g;

    int buf = 0;
    for (int kt = 0; kt < 25; kt++) {            // kt == conv position
        int p5 = kt / 5;
        int dh = p5 - 2, dw = kt - p5 * 5 - 2;
        int prow = (hbase + dh + 2) * 68 + wbase + dw + 2;

        uint32_t af[2][4];
        #pragma unroll
        for (int tm = 0; tm < 2; tm++) {
            int px = prow + tm * 16;
            af[tm][0] = *(const uint32_t*)&patch[px * PPITCH + 2 * tig];
            af[tm][1] = *(const uint32_t*)&patch[(px + 8) * PPITCH + 2 * tig];
            af[tm][2] = *(const uint32_t*)&patch[px * PPITCH + 2 * tig + 8];
            af[tm][3] = *(const uint32_t*)&patch[(px + 8) * PPITCH + 2 * tig + 8];
        }
        uint2 bf[8];
        #pragma unroll
        for (int tn = 0; tn < 8; tn++)
            bf[tn] = sB[buf][(wnn * 8 + tn) * 32 + lane];
        #pragma unroll
        for (int tm = 0; tm < 2; tm++)
            #pragma unroll
            for (int tn = 0; tn < 8; tn++)
                MMA_F16(acc[tm][tn], af[tm][0], af[tm][1], af[tm][2], af[tm][3], bf[tn]);

        if (kt < 24) {
            stsB(buf ^ 1);
            __syncthreads();
            if (kt < 23) loadB(kt + 2);
            buf ^= 1;
        }
    }

    // epilogue: c0=(g,2tig) c1=(g,2tig+1) c2=(g+8,2tig) c3=(g+8,2tig+1) -> fp16
    #pragma unroll
    for (int tm = 0; tm < 2; tm++) {
        #pragma unroll
        for (int tn = 0; tn < 8; tn++) {
            int row0 = wm * 32 + tm * 16 + g;
            int col  = wnn * 64 + tn * 8 + 2 * tig;
            #pragma unroll
            for (int rr = 0; rr < 2; rr++) {
                int row = row0 + rr * 8;
                int hh = row >> 6, w = row & 63;
                __half* ob = g_uhat +
                    ((((size_t)(ic * NB + nb) * HH + h0 + hh) * WWs + w) * ODIM + col);
                *(uint32_t*)ob = pack_h2(acc[tm][tn][rr * 2], acc[tm][tn][rr * 2 + 1]);
            }
        }
    }
}

// =================================================================================
// pvb: b-update via Gram trick. Thread = (pixel, o); no smem; fp16 uhat loads.
// =================================================================================
__global__ void __launch_bounds__(128, 3) pvb_kernel(int mode) {
    const int t = threadIdx.x;
    const int o = t & 7, p = t >> 3;            // 16 pixels x 8 o per block
    const int P = blockIdx.x * 16 + p;
    const int n = P >> 12, hw = P & 4095;

    float r[8];
    if (mode == 0) {
        int h = hw >> 6, w = hw & 63;
        int ch = min(h + 2, HH - 1) - max(h - 2, 0) + 1;
        int cw = min(w + 2, WWs - 1) - max(w - 2, 0) + 1;
        float r0 = 1.f / (8.f * (float)(ch * cw));
        #pragma unroll
        for (int j = 0; j < 8; j++) r[j] = r0;
    } else {
        #pragma unroll
        for (int j = 0; j < 8; j++)
            r[j] = g_r[((size_t)(j * NB + n) * NO + o) * HWs + hw];
    }

    float G[36];
    #pragma unroll
    for (int k = 0; k < 36; k++) G[k] = 0.f;

    const size_t ubase = ((size_t)n * HWs + hw) * ODIM + o * 16;
    const size_t istr = (size_t)NB * HWs * ODIM;
    #pragma unroll
    for (int d4 = 0; d4 < 4; d4++) {
        float4 u[8];
        #pragma unroll
        for (int i = 0; i < 8; i++) {
            uint2 v = *(const uint2*)(g_uhat + ubase + istr * i + d4 * 4);
            __half2* hp = (__half2*)&v;
            float2 f0 = __half22float2(hp[0]);
            float2 f1 = __half22float2(hp[1]);
            u[i] = make_float4(f0.x, f0.y, f1.x, f1.y);
        }
        int idx = 0;
        #pragma unroll
        for (int i = 0; i < 8; i++)
            #pragma unroll
            for (int j = i; j < 8; j++, idx++)
                G[idx] += u[i].x * u[j].x + u[i].y * u[j].y
                        + u[i].z * u[j].z + u[i].w * u[j].w;
    }

    float s[8];
    #pragma unroll
    for (int i = 0; i < 8; i++) s[i] = 0.f;
    {
        int idx = 0;
        #pragma unroll
        for (int i = 0; i < 8; i++)
            #pragma unroll
            for (int j = i; j < 8; j++, idx++) {
                s[i] += r[j] * G[idx];
                if (j > i) s[j] += r[i] * G[idx];
            }
    }
    float ns = 0.f;
    #pragma unroll
    for (int i = 0; i < 8; i++) ns += r[i] * s[i];
    float scale = ns / ((1.f + ns) * sqrtf(ns + 1e-9f));

    #pragma unroll
    for (int i = 0; i < 8; i++) {
        size_t bi = ((size_t)(i * NB + n) * NO + o) * HWs + hw;
        float a = scale * s[i];
        g_b[bi] = (mode == 0) ? a : g_b[bi] + a;
    }
}

// =================================================================================
// pvout: final iteration — stream p, squash, write fp32 output.
// =================================================================================
__global__ void __launch_bounds__(128, 4) pvout_kernel(float* __restrict__ out) {
    const int t = threadIdx.x;
    const int o = t & 7, p = t >> 3;
    const int P = blockIdx.x * 16 + p;
    const int n = P >> 12, hw = P & 4095;

    float r[8];
    #pragma unroll
    for (int j = 0; j < 8; j++)
        r[j] = g_r[((size_t)(j * NB + n) * NO + o) * HWs + hw];

    float pv[16];
    #pragma unroll
    for (int d = 0; d < 16; d++) pv[d] = 0.f;

    const size_t ubase = ((size_t)n * HWs + hw) * ODIM + o * 16;
    const size_t istr = (size_t)NB * HWs * ODIM;
    #pragma unroll
    for (int d4 = 0; d4 < 4; d4++) {
        #pragma unroll
        for (int i = 0; i < 8; i++) {
            uint2 v = *(const uint2*)(g_uhat + ubase + istr * i + d4 * 4);
            __half2* hp = (__half2*)&v;
            float2 f0 = __half22float2(hp[0]);
            float2 f1 = __half22float2(hp[1]);
            pv[d4 * 4 + 0] += r[i] * f0.x;
            pv[d4 * 4 + 1] += r[i] * f0.y;
            pv[d4 * 4 + 2] += r[i] * f1.x;
            pv[d4 * 4 + 3] += r[i] * f1.y;
        }
    }

    float ns = 0.f;
    #pragma unroll
    for (int d = 0; d < 16; d++) ns += pv[d] * pv[d];
    float scale = ns / ((1.f + ns) * sqrtf(ns + 1e-9f));

    #pragma unroll
    for (int d = 0; d < 16; d++)
        out[(((size_t)n * NO + o) * DCAP + d) * HWs + hw] = pv[d] * scale;
}

// =================================================================================
// R kernels (unchanged)
// =================================================================================
__global__ void rk1_kernel() {
    int idx = blockIdx.x * 256 + threadIdx.x;
    int in = idx >> 12, hw = idx & 4095;
    const float* bb = g_b + (size_t)in * NO * HWs + hw;
    float m = bb[0];
    #pragma unroll
    for (int o = 1; o < NO; o++) m = fmaxf(m, bb[(size_t)o * HWs]);
    g_t[idx] = m;
}

__global__ void rk2_kernel() {
    int idx = blockIdx.x * 256 + threadIdx.x;
    int in = idx >> 12, hw = idx & 4095, h = hw >> 6, w = hw & 63;
    const float* tb = g_t + (size_t)in * HWs;
    float m = -3.4e38f;
    #pragma unroll
    for (int dh = -2; dh <= 2; dh++) {
        int hh = h + dh;
        if ((unsigned)hh < HH) {
            #pragma unroll
            for (int dw = -2; dw <= 2; dw++) {
                int ww = w + dw;
                if ((unsigned)ww < WWs) m = fmaxf(m, tb[hh * WWs + ww]);
            }
        }
    }
    const float* bb = g_b + (size_t)in * NO * HWs + hw;
    float s = 0.f;
    #pragma unroll
    for (int o = 0; o < NO; o++) s += __expf(bb[(size_t)o * HWs] - m);
    g_bm[idx] = m;
    g_sc[idx] = s;
}

__global__ void rk3_kernel() {
    int idx = blockIdx.x * 256 + threadIdx.x;
    int in = idx >> 12, hw = idx & 4095, h = hw >> 6, w = hw & 63;
    const float* scb = g_sc + (size_t)in * HWs;
    float ss = 0.f;
    #pragma unroll
    for (int dh = -2; dh <= 2; dh++) {
        int hh = h + dh;
        if ((unsigned)hh < HH) {
            #pragma unroll
            for (int dw = -2; dw <= 2; dw++) {
                int ww = w + dw;
                if ((unsigned)ww < WWs) ss += scb[hh * WWs + ww];
            }
        }
    }
    float bm  = g_bm[idx];
    float inv = 1.f / ss;
    const float* bb = g_b + (size_t)in * NO * HWs + hw;
    float*       rr = g_r + (size_t)in * NO * HWs + hw;
    #pragma unroll
    for (int o = 0; o < NO; o++)
        rr[(size_t)o * HWs] = __expf(bb[(size_t)o * HWs] - bm) * inv;
}

// =================================================================================
extern "C" void kernel_launch(void* const* d_in, const int* in_sizes, int n_in,
                              void* d_out, int out_size) {
    const float* u  = (const float*)d_in[0];   // [8, 8, 16, 64, 64]
    const float* Wp = (const float*)d_in[1];   // [8, 128, 16, 5, 5]
    float* out = (float*)d_out;                // [8, 8, 16, 64, 64]

    trans_kernel<<<NB * NI, 256>>>(u);
    repack_kernel<<<NI * 25, 512>>>(Wp);
    conv_mma_kernel<<<dim3(HH / 2, NB, NI), 256>>>();

    // routing iteration 0 (b = 0 -> analytic r)
    pvb_kernel<<<NB * HWs / 16, 128>>>(0);

    // routing iteration 1
    rk1_kernel<<<1024, 256>>>();
    rk2_kernel<<<1024, 256>>>();
    rk3_kernel<<<1024, 256>>>();
    pvb_kernel<<<NB * HWs / 16, 128>>>(1);

    // routing iteration 2 (final output)
    rk1_kernel<<<1024, 256>>>();
    rk2_kernel<<<1024, 256>>>();
    rk3_kernel<<<1024, 256>>>();
    pvout_kernel<<<NB * HWs / 16, 128>>>(out);
}